// round 10
// baseline (speedup 1.0000x reference)
#include <cuda_runtime.h>
#include <math.h>

#define NN 5000
#define EE 80000
#define FIN 32
#define DD 64
#define P1C 256
#define P2C 32
#define HH 256
#define MMROWS (NN + P1C + P2C)  /* 5288 */
#define LOG_SCALE 1.4763057f
#define BITWORDS ((NN*NN+31)/32)
#define RPB 8                     /* decoder rows per block */

// ---------------- scratch (__device__ globals; no allocation allowed) ----------
__device__ float g_z [NN*DD];
__device__ float g_P [NN*P1C];      // logits -> S (level 1), in place
__device__ float g_T1[NN*DD];
__device__ float g_ze[NN*DD];
__device__ float g_B [NN*P1C];      // A @ S
__device__ float g_x1[P1C*DD];
__device__ float g_A1[P1C*P1C];
__device__ float g_y1[P1C];
__device__ float g_P2[P1C*P2C];     // logits2 -> S2 in place
__device__ float g_T2[P1C*DD];
__device__ float g_ze2[P1C*DD];
__device__ float g_x2[P2C*DD];
__device__ float g_y2[P2C];
__device__ float g_b1p[HH], g_c1[HH], g_c2[HH];
__device__ float g_acc[8];          // 0:data 1:pde 2:ent1 3:ent2
__device__ unsigned g_bitmap[BITWORDS];
__device__ int g_deg[NN], g_cur[NN], g_offs[NN+1];
__device__ int g_csr[EE];
__device__ unsigned char g_keep[EE];

// ---------------- zero all per-call accumulators --------------------------------
__global__ void k_zero_all() {
    int i = blockIdx.x * blockDim.x + threadIdx.x;
    int st = gridDim.x * blockDim.x;
    for (int k = i; k < BITWORDS; k += st) g_bitmap[k] = 0u;
    for (int k = i; k < NN; k += st) { g_deg[k] = 0; g_cur[k] = 0; }
    for (int k = i; k < P1C*DD; k += st) g_x1[k] = 0.f;
    for (int k = i; k < P1C*P1C; k += st) g_A1[k] = 0.f;
    for (int k = i; k < P2C*DD; k += st) g_x2[k] = 0.f;
    if (i < 8) g_acc[i] = 0.f;
}

// ---------------- decoder constant prep (t_enc folded into b1', c1, c2) --------
__global__ void k_prep(const float* __restrict__ t, const float* __restrict__ W1,
                       const float* __restrict__ b1, const float* __restrict__ W2) {
    int h = threadIdx.x;
    float t0 = t[0];
    float te[6];
    te[0] = t0 / 1e2f;  te[1] = t0 / 1e3f;  te[2] = t0 / 1e4f;
    te[3] = logf(t0 / 1e-2f + 1.f);
    te[4] = logf(t0 / 1e-1f + 1.f);
    te[5] = logf(t0 / 1.0f  + 1.f);
    float b = b1[h];
    #pragma unroll
    for (int k = 0; k < 6; k++) b += te[k] * W1[k*HH + h];
    g_b1p[h] = b;
    float w2 = W2[h];
    g_c1[h] = w2 * W1[0*HH + h];
    float s = 0.f;
    #pragma unroll
    for (int k = 1; k < 9; k++) { float w = W1[k*HH + h]; s += w * w; }
    g_c2[h] = w2 * s;
}

// ---------------- encoder: z = tanh(x0 @ W_enc[:, :64]) * LOG_SCALE ------------
__global__ void k_encoder(const float* __restrict__ x0, const float* __restrict__ Wenc) {
    __shared__ float xs[16][FIN];
    int i0 = blockIdx.x * 16;
    int tid = threadIdx.x;
    #pragma unroll
    for (int q = 0; q < 2; q++) {
        int idx = tid + q*256;
        int r = idx >> 5, c = idx & 31;
        int gi = i0 + r;
        xs[r][c] = (gi < NN) ? x0[gi*FIN + c] : 0.f;
    }
    __syncthreads();
    int a = tid & 63, rg = tid >> 6;
    float acc[4] = {0.f, 0.f, 0.f, 0.f};
    #pragma unroll
    for (int d = 0; d < FIN; d++) {
        float w = Wenc[d*67 + a];           // W_enc is [32, 67]; need cols 0..63
        #pragma unroll
        for (int k = 0; k < 4; k++) acc[k] += xs[rg*4 + k][d] * w;
    }
    #pragma unroll
    for (int k = 0; k < 4; k++) {
        int gi = i0 + rg*4 + k;
        if (gi < NN) g_z[gi*DD + a] = tanhf(acc[k]) * LOG_SCALE;
    }
}

// ---------------- fused: P = (z@Wp1)*LOG_SCALE and T1 = z@We1 ------------------
// Both consume the same 16x64 z tile; stage once, compute both.
__global__ void k_PT1(const float* __restrict__ Wp, const float* __restrict__ We) {
    __shared__ float xs[16][DD];
    int i0 = blockIdx.x * 16;
    int tid = threadIdx.x;
    #pragma unroll
    for (int q = 0; q < 4; q++) {
        int idx = tid + q*256;
        int r = idx >> 6, c = idx & 63;
        int gi = i0 + r;
        xs[r][c] = (gi < NN) ? g_z[gi*DD + c] : 0.f;
    }
    __syncthreads();

    // phase 1: P (each thread one of 256 columns, 16 rows)
    {
        int a = tid;
        float acc[16];
        #pragma unroll
        for (int r = 0; r < 16; r++) acc[r] = 0.f;
        for (int d = 0; d < DD; d++) {
            float w = Wp[d*P1C + a];
            #pragma unroll
            for (int r = 0; r < 16; r++) acc[r] += xs[r][d] * w;
        }
        #pragma unroll
        for (int r = 0; r < 16; r++) {
            int gi = i0 + r;
            if (gi < NN) g_P[gi*P1C + a] = acc[r] * LOG_SCALE;
        }
    }

    // phase 2: T1 (64 columns x 4 row-groups)
    {
        int a = tid & 63, rg = tid >> 6;
        float acc[4] = {0.f, 0.f, 0.f, 0.f};
        for (int d = 0; d < DD; d++) {
            float w = We[d*DD + a];
            #pragma unroll
            for (int k = 0; k < 4; k++) acc[k] += xs[rg*4 + k][d] * w;
        }
        #pragma unroll
        for (int k = 0; k < 4; k++) {
            int gi = i0 + rg*4 + k;
            if (gi < NN) g_T1[gi*DD + a] = acc[k];
        }
    }
}

// ---------------- edge dedup (A = set(1.0) semantics) + degree count -----------
__global__ void k_dedup_count(const int* __restrict__ adj) {
    int e = blockIdx.x * blockDim.x + threadIdx.x;
    if (e >= EE) return;
    int i = adj[e], j = adj[EE + e];
    unsigned idx = (unsigned)i * NN + (unsigned)j;
    unsigned w = idx >> 5, b = 1u << (idx & 31);
    unsigned old = atomicOr(&g_bitmap[w], b);
    unsigned char kp = ((old & b) == 0u) ? 1 : 0;
    g_keep[e] = kp;
    if (kp) atomicAdd(&g_deg[i], 1);
}

// ---------------- exclusive scan of degrees (single block) ---------------------
__global__ void k_scan() {
    __shared__ int part[1024];
    int tid = threadIdx.x;
    int loc[5];
    int s = 0;
    #pragma unroll
    for (int k = 0; k < 5; k++) {
        int idx = tid*5 + k;
        int v = (idx < NN) ? g_deg[idx] : 0;
        loc[k] = s; s += v;
    }
    part[tid] = s;
    __syncthreads();
    for (int off = 1; off < 1024; off <<= 1) {
        int v = (tid >= off) ? part[tid - off] : 0;
        __syncthreads();
        part[tid] += v;
        __syncthreads();
    }
    int base = (tid > 0) ? part[tid - 1] : 0;
    #pragma unroll
    for (int k = 0; k < 5; k++) {
        int idx = tid*5 + k;
        if (idx < NN) g_offs[idx] = base + loc[k];
    }
    if (tid == 1023) g_offs[NN] = part[1023];
}

// ---------------- fill CSR column indices --------------------------------------
__global__ void k_fill(const int* __restrict__ adj) {
    int e = blockIdx.x * blockDim.x + threadIdx.x;
    if (e >= EE) return;
    if (!g_keep[e]) return;
    int i = adj[e], j = adj[EE + e];
    int p = atomicAdd(&g_cur[i], 1);
    g_csr[g_offs[i] + p] = j;
}

// ---------------- ze = tanh(A @ T1) via CSR gather -----------------------------
__global__ void k_gather_ze() {
    int row = blockIdx.x * 4 + threadIdx.y;
    if (row >= NN) return;
    int d = threadIdx.x;
    int s = g_offs[row], e = g_offs[row + 1];
    float acc = 0.f;
    for (int p = s; p < e; p++) {
        int j = g_csr[p];
        acc += g_T1[j*DD + d];
    }
    g_ze[row*DD + d] = tanhf(acc);
}

// ---------------- column softmax (axis=0) + entropy + y1 pooling ---------------
// Coalesced layout: block = (32 cols, 32 row-lanes). Warp reads 32 consecutive
// columns of one row (128B). Per-column reductions across threadIdx.y via shared.
__global__ void k_softmax1(const float* __restrict__ y) {
    __shared__ float sm[32][33];
    int txc = threadIdx.x;
    int ty  = threadIdx.y;
    int col = blockIdx.x * 32 + txc;

    // pass 1: column max
    float m = -1e30f;
    for (int i = ty; i < NN; i += 32) m = fmaxf(m, g_P[i*P1C + col]);
    sm[ty][txc] = m; __syncthreads();
    for (int s = 16; s; s >>= 1) {
        if (ty < s) sm[ty][txc] = fmaxf(sm[ty][txc], sm[ty+s][txc]);
        __syncthreads();
    }
    float mx = sm[0][txc]; __syncthreads();

    // pass 2: sum of exp
    float z = 0.f;
    for (int i = ty; i < NN; i += 32) z += expf(g_P[i*P1C + col] - mx);
    sm[ty][txc] = z; __syncthreads();
    for (int s = 16; s; s >>= 1) {
        if (ty < s) sm[ty][txc] += sm[ty+s][txc];
        __syncthreads();
    }
    float Z = sm[0][txc]; __syncthreads();
    float inv = 1.f / Z;
    float lZ  = logf(Z);

    // pass 3: write S, entropy (-sv*ln sv via identity), y-pool
    float ent = 0.f, ya = 0.f;
    for (int i = ty; i < NN; i += 32) {
        float v  = g_P[i*P1C + col];
        float sv = expf(v - mx) * inv;
        g_P[i*P1C + col] = sv;
        ent -= sv * ((v - mx) - lZ);
        ya  += y[i] * sv;
    }
    sm[ty][txc] = ya; __syncthreads();
    for (int s = 16; s; s >>= 1) {
        if (ty < s) sm[ty][txc] += sm[ty+s][txc];
        __syncthreads();
    }
    if (ty == 0) g_y1[col] = sm[0][txc] * ((float)P1C / (float)NN);
    __syncthreads();
    sm[ty][txc] = ent; __syncthreads();
    for (int s = 16; s; s >>= 1) {
        if (ty < s) sm[ty][txc] += sm[ty+s][txc];
        __syncthreads();
    }
    if (ty == 0) {
        float e = sm[0][txc];
        #pragma unroll
        for (int o = 16; o; o >>= 1) e += __shfl_xor_sync(0xffffffffu, e, o);
        if (txc == 0) atomicAdd(&g_acc[2], e);
    }
}

// ---------------- B = A @ S via CSR gather  [5000,256] -------------------------
__global__ void k_gather_B() {
    int row = blockIdx.x, a = threadIdx.x;
    int s = g_offs[row], e = g_offs[row + 1];
    float acc = 0.f;
    for (int p = s; p < e; p++) {
        int j = g_csr[p];
        acc += g_P[j*P1C + a];
    }
    g_B[row*P1C + a] = acc;
}

// ---------------- generic C += scale * A^T B, K-split via blockIdx.z -----------
__device__ __forceinline__ void gemm_AtB_dev(const float* __restrict__ A,
                                             const float* __restrict__ B,
                                             float* __restrict__ C,
                                             int K, int Mdim, int Ndim,
                                             int kPer, float scale) {
    __shared__ float As[16][65];
    __shared__ float Bs[16][65];
    int m0 = blockIdx.x * 64, n0 = blockIdx.y * 64;
    int k0 = blockIdx.z * kPer;
    int kEnd = min(K, k0 + kPer);
    int tid = threadIdx.x;
    int tx = tid & 15, ty = tid >> 4;
    float acc[4][4];
    #pragma unroll
    for (int i = 0; i < 4; i++)
        #pragma unroll
        for (int j = 0; j < 4; j++) acc[i][j] = 0.f;
    for (int kb = k0; kb < kEnd; kb += 16) {
        #pragma unroll
        for (int q = 0; q < 4; q++) {
            int idx = tid + q*256;
            int kk = idx >> 6, mm = idx & 63;
            int kg = kb + kk;
            As[kk][mm] = (kg < kEnd && (m0 + mm) < Mdim) ? A[kg*Mdim + m0 + mm] : 0.f;
            Bs[kk][mm] = (kg < kEnd && (n0 + mm) < Ndim) ? B[kg*Ndim + n0 + mm] : 0.f;
        }
        __syncthreads();
        #pragma unroll
        for (int kk = 0; kk < 16; kk++) {
            float av[4], bv[4];
            #pragma unroll
            for (int i = 0; i < 4; i++) av[i] = As[kk][ty*4 + i];
            #pragma unroll
            for (int j = 0; j < 4; j++) bv[j] = Bs[kk][tx*4 + j];
            #pragma unroll
            for (int i = 0; i < 4; i++)
                #pragma unroll
                for (int j = 0; j < 4; j++) acc[i][j] += av[i] * bv[j];
        }
        __syncthreads();
    }
    #pragma unroll
    for (int i = 0; i < 4; i++) {
        int m = m0 + ty*4 + i;
        if (m >= Mdim) continue;
        #pragma unroll
        for (int j = 0; j < 4; j++) {
            int n = n0 + tx*4 + j;
            if (n < Ndim) atomicAdd(&C[m*Ndim + n], acc[i][j] * scale);
        }
    }
}

__global__ void k_gemm_x1() { gemm_AtB_dev(g_P,  g_ze,  g_x1, NN,  P1C, DD,  625, (float)P1C/(float)NN); }
__global__ void k_gemm_A1() { gemm_AtB_dev(g_P,  g_B,   g_A1, NN,  P1C, P1C, 625, 1.f); }
__global__ void k_gemm_x2() { gemm_AtB_dev(g_P2, g_ze2, g_x2, P1C, P2C, DD,  256, (float)P2C/(float)P1C); }

// ---------------- fused level-2: P2 = (x1@Wp2)*LOG_SCALE and T2 = x1@We2 -------
// Flat dispatch: indices [0, P1C*P2C) -> P2, [P1C*P2C, P1C*P2C + P1C*DD) -> T2.
__global__ void k_PT2(const float* __restrict__ Wp2, const float* __restrict__ We2) {
    int idx = blockIdx.x * blockDim.x + threadIdx.x;
    if (idx < P1C*P2C) {
        int i = idx / P2C, a = idx % P2C;
        float acc = 0.f;
        for (int d = 0; d < DD; d++) acc += g_x1[i*DD + d] * Wp2[d*P2C + a];
        g_P2[idx] = acc * LOG_SCALE;
    } else {
        int r = idx - P1C*P2C;
        if (r >= P1C*DD) return;
        int i = r / DD, d = r % DD;
        float acc = 0.f;
        for (int k = 0; k < DD; k++) acc += g_x1[i*DD + k] * We2[k*DD + d];
        g_T2[r] = acc;
    }
}

__global__ void k_softmax2() {
    __shared__ float sm[256];
    int a = blockIdx.x, tid = threadIdx.x;
    float v = g_P2[tid*P2C + a];
    sm[tid] = v; __syncthreads();
    for (int s = 128; s; s >>= 1) { if (tid < s) sm[tid] = fmaxf(sm[tid], sm[tid+s]); __syncthreads(); }
    float mx = sm[0]; __syncthreads();
    float e = expf(v - mx);
    sm[tid] = e; __syncthreads();
    for (int s = 128; s; s >>= 1) { if (tid < s) sm[tid] += sm[tid+s]; __syncthreads(); }
    float Z = sm[0]; __syncthreads();
    float sv = e / Z;
    g_P2[tid*P2C + a] = sv;
    float ent = (sv > 0.f) ? -sv * logf(sv) : 0.f;
    sm[tid] = ent; __syncthreads();
    for (int s = 128; s; s >>= 1) { if (tid < s) sm[tid] += sm[tid+s]; __syncthreads(); }
    float E = sm[0]; __syncthreads();
    float ya = g_y1[tid] * sv;
    sm[tid] = ya; __syncthreads();
    for (int s = 128; s; s >>= 1) { if (tid < s) sm[tid] += sm[tid+s]; __syncthreads(); }
    if (tid == 0) {
        atomicAdd(&g_acc[3], E);
        g_y2[a] = sm[0] * ((float)P2C / (float)P1C);
    }
}

__global__ void k_ze2() {
    int i = blockIdx.x, d = threadIdx.x;
    float acc = 0.f;
    #pragma unroll 4
    for (int j = 0; j < P1C; j++) acc += g_A1[i*P1C + j] * g_T2[j*DD + d];
    g_ze2[i*DD + d] = tanhf(acc);
}

// ---------------- decoder: 8 rows/block, analytic grad/lap, fused losses -------
__global__ void k_decoder(const float* __restrict__ y, const float* __restrict__ W1,
                          const float* __restrict__ W2, const float* __restrict__ b2) {
    __shared__ float zr[RPB][DD];
    __shared__ float yv[RPB];
    __shared__ float part[8][RPB][2];   // [warp][row][u|res]
    __shared__ float fin[RPB][2];
    int base = blockIdx.x * RPB;
    int tid = threadIdx.x;

    // stage 8 rows of z_r and y_r
    #pragma unroll
    for (int q = 0; q < 2; q++) {
        int idx = tid + q*256;
        int r = idx >> 6, d = idx & 63;
        int row = base + r;
        float v = 0.f;
        if (row < MMROWS) {
            const float* src = (row < NN) ? &g_z[row*DD]
                             : (row < NN+P1C ? &g_x1[(row-NN)*DD] : &g_x2[(row-NN-P1C)*DD]);
            v = src[d];
        }
        zr[r][d] = v;
    }
    if (tid < RPB) {
        int row = base + tid;
        float v = 0.f;
        if (row < MMROWS)
            v = (row < NN) ? y[row] : (row < NN+P1C ? g_y1[row-NN] : g_y2[row-NN-P1C]);
        yv[tid] = v;
    }
    __syncthreads();

    int h = tid;
    float bh  = g_b1p[h];
    float w2h = W2[h];
    float c1h = g_c1[h];
    float c2h = g_c2[h];

    float a[RPB];
    #pragma unroll
    for (int r = 0; r < RPB; r++) a[r] = bh;
    for (int d = 0; d < DD; d++) {
        float w = W1[(9 + d)*HH + h];
        #pragma unroll
        for (int r = 0; r < RPB; r++) a[r] += zr[r][d] * w;
    }

    float uc[RPB], rc[RPB];
    #pragma unroll
    for (int r = 0; r < RPB; r++) {
        float th = tanhf(a[r]);
        float dh = 1.f - th*th;
        uc[r] = w2h * th;
        rc[r] = c1h * dh + 2.f * th * dh * c2h;   // grad - lap contribution
    }

    // warp reduce each value, lane0 writes partials
    int lane = tid & 31, wrp = tid >> 5;
    #pragma unroll
    for (int r = 0; r < RPB; r++) {
        float u = uc[r], rr = rc[r];
        #pragma unroll
        for (int o = 16; o; o >>= 1) {
            u  += __shfl_xor_sync(0xffffffffu, u,  o);
            rr += __shfl_xor_sync(0xffffffffu, rr, o);
        }
        if (lane == 0) { part[wrp][r][0] = u; part[wrp][r][1] = rr; }
    }
    __syncthreads();

    if (tid < RPB) {
        int r = tid;
        float U = 0.f, R = 0.f;
        #pragma unroll
        for (int w = 0; w < 8; w++) { U += part[w][r][0]; R += part[w][r][1]; }
        int row = base + r;
        if (row < MMROWS) {
            float ed = U + b2[0] - yv[r];
            fin[r][0] = ed * ed;
            fin[r][1] = R * R;
        } else {
            fin[r][0] = 0.f; fin[r][1] = 0.f;
        }
    }
    __syncthreads();
    if (tid == 0) {
        float sd = 0.f, sp = 0.f;
        #pragma unroll
        for (int r = 0; r < RPB; r++) { sd += fin[r][0]; sp += fin[r][1]; }
        atomicAdd(&g_acc[0], sd);
        atomicAdd(&g_acc[1], sp);
    }
}

// ---------------- final scalar -------------------------------------------------
__global__ void k_final(float* __restrict__ out) {
    float loss = g_acc[0] / (float)MMROWS
               + g_acc[1] / (float)MMROWS
               + g_acc[2] / (float)(NN*P1C)
               + g_acc[3] / (float)(P1C*P2C);
    out[0] = loss;
}

// ---------------- launch --------------------------------------------------------
extern "C" void kernel_launch(void* const* d_in, const int* in_sizes, int n_in,
                              void* d_out, int out_size) {
    const float* x0   = (const float*)d_in[0];
    const int*   adj  = (const int*)  d_in[1];
    const float* t    = (const float*)d_in[2];
    const float* y    = (const float*)d_in[3];
    const float* Wenc = (const float*)d_in[4];
    const float* Wp1  = (const float*)d_in[5];
    const float* Wp2  = (const float*)d_in[6];
    const float* We1  = (const float*)d_in[7];
    const float* We2  = (const float*)d_in[8];
    const float* W1   = (const float*)d_in[9];
    const float* b1   = (const float*)d_in[10];
    const float* W2   = (const float*)d_in[11];
    const float* b2   = (const float*)d_in[12];
    float* out = (float*)d_out;

    k_zero_all<<<1024, 256>>>();
    k_prep<<<1, 256>>>(t, W1, b1, W2);
    k_encoder<<<(NN + 15)/16, 256>>>(x0, Wenc);
    k_PT1<<<(NN + 15)/16, 256>>>(Wp1, We1);
    k_dedup_count<<<(EE + 255)/256, 256>>>(adj);
    k_scan<<<1, 1024>>>();
    k_fill<<<(EE + 255)/256, 256>>>(adj);
    k_gather_ze<<<(NN + 3)/4, dim3(64, 4)>>>();
    k_softmax1<<<P1C/32, dim3(32, 32)>>>(y);
    k_gather_B<<<NN, 256>>>();
    k_gemm_x1<<<dim3(4, 1, 8), 256>>>();
    k_gemm_A1<<<dim3(4, 4, 8), 256>>>();
    k_PT2<<<(P1C*P2C + P1C*DD + 255)/256, 256>>>(Wp2, We2);
    k_softmax2<<<P2C, 256>>>();
    k_ze2<<<P1C, DD>>>();
    k_gemm_x2<<<dim3(1, 1, 1), 256>>>();
    k_decoder<<<(MMROWS + RPB - 1)/RPB, 256>>>(y, W1, W2, b2);
    k_final<<<1, 1>>>(out);
}

// round 12
// speedup vs baseline: 1.5049x; 1.5049x over previous
#include <cuda_runtime.h>
#include <math.h>

#define NN 5000
#define EE 80000
#define FIN 32
#define DD 64
#define P1C 256
#define P2C 32
#define HH 256
#define MMROWS (NN + P1C + P2C)  /* 5288 */
#define LOG_SCALE 1.4763057f
#define BITWORDS ((NN*NN+31)/32)
#define RPB 8                     /* decoder rows per block */

// ---------------- scratch (__device__ globals; no allocation allowed) ----------
__device__ float g_z [NN*DD];
__device__ float g_P [NN*P1C];      // logits -> S (level 1), in place
__device__ float g_T1[NN*DD];
__device__ float g_ze[NN*DD];
__device__ float g_B [NN*P1C];      // A @ S
__device__ float g_x1[P1C*DD];
__device__ float g_A1[P1C*P1C];
__device__ float g_y1[P1C];
__device__ float g_colZ[P1C];
__device__ float g_P2[P1C*P2C];     // logits2 -> S2 in place
__device__ float g_T2[P1C*DD];
__device__ float g_ze2[P1C*DD];
__device__ float g_x2[P2C*DD];
__device__ float g_y2[P2C];
__device__ float g_b1p[HH], g_c1[HH], g_c2[HH];
__device__ float g_acc[8];          // 0:data 1:pde 2:ent1 3:ent2
__device__ unsigned g_bitmap[BITWORDS];
__device__ int g_deg[NN], g_cur[NN], g_offs[NN+1];
__device__ int g_csr[EE];
__device__ unsigned char g_keep[EE];

// ---------------- zero all per-call accumulators --------------------------------
__global__ void k_zero_all() {
    int i = blockIdx.x * blockDim.x + threadIdx.x;
    int st = gridDim.x * blockDim.x;
    for (int k = i; k < BITWORDS; k += st) g_bitmap[k] = 0u;
    for (int k = i; k < NN; k += st) { g_deg[k] = 0; g_cur[k] = 0; }
    for (int k = i; k < P1C*DD; k += st) g_x1[k] = 0.f;
    for (int k = i; k < P1C*P1C; k += st) g_A1[k] = 0.f;
    for (int k = i; k < P2C*DD; k += st) g_x2[k] = 0.f;
    for (int k = i; k < P1C; k += st) { g_y1[k] = 0.f; g_colZ[k] = 0.f; }
    if (i < 8) g_acc[i] = 0.f;
}

// ---------------- decoder constant prep (t_enc folded into b1', c1, c2) --------
__global__ void k_prep(const float* __restrict__ t, const float* __restrict__ W1,
                       const float* __restrict__ b1, const float* __restrict__ W2) {
    int h = threadIdx.x;
    float t0 = t[0];
    float te[6];
    te[0] = t0 / 1e2f;  te[1] = t0 / 1e3f;  te[2] = t0 / 1e4f;
    te[3] = logf(t0 / 1e-2f + 1.f);
    te[4] = logf(t0 / 1e-1f + 1.f);
    te[5] = logf(t0 / 1.0f  + 1.f);
    float b = b1[h];
    #pragma unroll
    for (int k = 0; k < 6; k++) b += te[k] * W1[k*HH + h];
    g_b1p[h] = b;
    float w2 = W2[h];
    g_c1[h] = w2 * W1[0*HH + h];
    float s = 0.f;
    #pragma unroll
    for (int k = 1; k < 9; k++) { float w = W1[k*HH + h]; s += w * w; }
    g_c2[h] = w2 * s;
}

// ---------------- encoder: z = tanh(x0 @ W_enc[:, :64]) * LOG_SCALE ------------
// 8 rows/block (625 blocks), batched weight loads for MLP.
__global__ void k_encoder(const float* __restrict__ x0, const float* __restrict__ Wenc) {
    __shared__ float xs[8][FIN];
    int i0 = blockIdx.x * 8;
    int tid = threadIdx.x;
    {
        int r = tid >> 5, c = tid & 31;
        xs[r][c] = x0[(i0 + r)*FIN + c];       // 625*8 = 5000 exact
    }
    __syncthreads();
    int a = tid & 63, rg = tid >> 6;           // rg 0..3 -> rows rg*2, rg*2+1
    float acc[2] = {0.f, 0.f};
    #pragma unroll
    for (int d0 = 0; d0 < FIN; d0 += 8) {
        float w[8];
        #pragma unroll
        for (int k = 0; k < 8; k++) w[k] = Wenc[(d0+k)*67 + a];
        #pragma unroll
        for (int k = 0; k < 8; k++) {
            acc[0] += xs[rg*2 + 0][d0+k] * w[k];
            acc[1] += xs[rg*2 + 1][d0+k] * w[k];
        }
    }
    #pragma unroll
    for (int r = 0; r < 2; r++)
        g_z[(i0 + rg*2 + r)*DD + a] = tanhf(acc[r]) * LOG_SCALE;
}

// ---------------- fused: P = (z@Wp1)*LOG_SCALE and T1 = z@We1 ------------------
// 8 rows/block (625 blocks); batched weight loads (MLP=8).
__global__ void k_PT1(const float* __restrict__ Wp, const float* __restrict__ We) {
    __shared__ float xs[8][DD];
    int i0 = blockIdx.x * 8;
    int tid = threadIdx.x;
    #pragma unroll
    for (int q = 0; q < 2; q++) {
        int idx = tid + q*256;
        int r = idx >> 6, c = idx & 63;
        xs[r][c] = g_z[(i0 + r)*DD + c];
    }
    __syncthreads();

    // phase 1: P (each thread one of 256 columns, 8 rows)
    {
        int a = tid;
        float acc[8];
        #pragma unroll
        for (int r = 0; r < 8; r++) acc[r] = 0.f;
        #pragma unroll
        for (int d0 = 0; d0 < DD; d0 += 8) {
            float w[8];
            #pragma unroll
            for (int k = 0; k < 8; k++) w[k] = Wp[(d0+k)*P1C + a];
            #pragma unroll
            for (int k = 0; k < 8; k++)
                #pragma unroll
                for (int r = 0; r < 8; r++) acc[r] += xs[r][d0+k] * w[k];
        }
        #pragma unroll
        for (int r = 0; r < 8; r++)
            g_P[(i0 + r)*P1C + a] = acc[r] * LOG_SCALE;
    }

    // phase 2: T1 (64 columns x 4 row-groups of 2 rows)
    {
        int a = tid & 63, rg = tid >> 6;
        float acc[2] = {0.f, 0.f};
        #pragma unroll
        for (int d0 = 0; d0 < DD; d0 += 8) {
            float w[8];
            #pragma unroll
            for (int k = 0; k < 8; k++) w[k] = We[(d0+k)*DD + a];
            #pragma unroll
            for (int k = 0; k < 8; k++) {
                acc[0] += xs[rg*2 + 0][d0+k] * w[k];
                acc[1] += xs[rg*2 + 1][d0+k] * w[k];
            }
        }
        #pragma unroll
        for (int r = 0; r < 2; r++)
            g_T1[(i0 + rg*2 + r)*DD + a] = acc[r];
    }
}

// ---------------- edge dedup (A = set(1.0) semantics) + degree count -----------
__global__ void k_dedup_count(const int* __restrict__ adj) {
    int e = blockIdx.x * blockDim.x + threadIdx.x;
    if (e >= EE) return;
    int i = adj[e], j = adj[EE + e];
    unsigned idx = (unsigned)i * NN + (unsigned)j;
    unsigned w = idx >> 5, b = 1u << (idx & 31);
    unsigned old = atomicOr(&g_bitmap[w], b);
    unsigned char kp = ((old & b) == 0u) ? 1 : 0;
    g_keep[e] = kp;
    if (kp) atomicAdd(&g_deg[i], 1);
}

// ---------------- exclusive scan of degrees (single block) ---------------------
__global__ void k_scan() {
    __shared__ int part[1024];
    int tid = threadIdx.x;
    int loc[5];
    int s = 0;
    #pragma unroll
    for (int k = 0; k < 5; k++) {
        int idx = tid*5 + k;
        int v = (idx < NN) ? g_deg[idx] : 0;
        loc[k] = s; s += v;
    }
    part[tid] = s;
    __syncthreads();
    for (int off = 1; off < 1024; off <<= 1) {
        int v = (tid >= off) ? part[tid - off] : 0;
        __syncthreads();
        part[tid] += v;
        __syncthreads();
    }
    int base = (tid > 0) ? part[tid - 1] : 0;
    #pragma unroll
    for (int k = 0; k < 5; k++) {
        int idx = tid*5 + k;
        if (idx < NN) g_offs[idx] = base + loc[k];
    }
    if (tid == 1023) g_offs[NN] = part[1023];
}

// ---------------- fill CSR column indices --------------------------------------
__global__ void k_fill(const int* __restrict__ adj) {
    int e = blockIdx.x * blockDim.x + threadIdx.x;
    if (e >= EE) return;
    if (!g_keep[e]) return;
    int i = adj[e], j = adj[EE + e];
    int p = atomicAdd(&g_cur[i], 1);
    g_csr[g_offs[i] + p] = j;
}

// ---------------- ze = tanh(A @ T1) via CSR gather (edge-unrolled x4) ----------
__global__ void k_gather_ze() {
    int row = blockIdx.x * 4 + threadIdx.y;
    if (row >= NN) return;
    int d = threadIdx.x;
    int s = g_offs[row], e = g_offs[row + 1];
    float acc = 0.f;
    int p = s;
    for (; p + 4 <= e; p += 4) {
        int j0 = g_csr[p], j1 = g_csr[p+1], j2 = g_csr[p+2], j3 = g_csr[p+3];
        acc += g_T1[j0*DD + d] + g_T1[j1*DD + d] + g_T1[j2*DD + d] + g_T1[j3*DD + d];
    }
    for (; p < e; p++) acc += g_T1[g_csr[p]*DD + d];
    g_ze[row*DD + d] = tanhf(acc);
}

// ---------------- softmax1 part 1: column sum of exp (no max; logits bounded) --
// grid (8 colgroups, 20 rowchunks), block (32 cols, 32 rows).
__global__ void k_soft1_partial() {
    __shared__ float sm[32][33];
    int txc = threadIdx.x, ty = threadIdx.y;
    int col = blockIdx.x * 32 + txc;
    int r0 = blockIdx.y * 250, r1 = r0 + 250;
    float z = 0.f;
    for (int i = r0 + ty; i < r1; i += 32) z += expf(g_P[i*P1C + col]);
    sm[ty][txc] = z; __syncthreads();
    for (int s = 16; s; s >>= 1) {
        if (ty < s) sm[ty][txc] += sm[ty+s][txc];
        __syncthreads();
    }
    if (ty == 0) atomicAdd(&g_colZ[col], sm[0][txc]);
}

// ---------------- softmax1 part 2: normalize + entropy + y-pool ----------------
__global__ void k_soft1_final(const float* __restrict__ y) {
    __shared__ float sm[32][33];
    int txc = threadIdx.x, ty = threadIdx.y;
    int col = blockIdx.x * 32 + txc;
    int r0 = blockIdx.y * 250, r1 = r0 + 250;
    float Z = g_colZ[col];
    float inv = 1.f / Z;
    float lZ  = logf(Z);
    float ent = 0.f, ya = 0.f;
    for (int i = r0 + ty; i < r1; i += 32) {
        float v  = g_P[i*P1C + col];
        float sv = expf(v) * inv;
        g_P[i*P1C + col] = sv;
        ent -= sv * (v - lZ);
        ya  += y[i] * sv;
    }
    sm[ty][txc] = ya; __syncthreads();
    for (int s = 16; s; s >>= 1) {
        if (ty < s) sm[ty][txc] += sm[ty+s][txc];
        __syncthreads();
    }
    if (ty == 0) atomicAdd(&g_y1[col], sm[0][txc] * ((float)P1C / (float)NN));
    __syncthreads();
    sm[ty][txc] = ent; __syncthreads();
    for (int s = 16; s; s >>= 1) {
        if (ty < s) sm[ty][txc] += sm[ty+s][txc];
        __syncthreads();
    }
    if (ty == 0) {
        float e = sm[0][txc];
        #pragma unroll
        for (int o = 16; o; o >>= 1) e += __shfl_xor_sync(0xffffffffu, e, o);
        if (txc == 0) atomicAdd(&g_acc[2], e);
    }
}

// ---------------- B = A @ S via CSR gather (edge-unrolled x4) ------------------
__global__ void k_gather_B() {
    int row = blockIdx.x, a = threadIdx.x;
    int s = g_offs[row], e = g_offs[row + 1];
    float acc = 0.f;
    int p = s;
    for (; p + 4 <= e; p += 4) {
        int j0 = g_csr[p], j1 = g_csr[p+1], j2 = g_csr[p+2], j3 = g_csr[p+3];
        acc += g_P[j0*P1C + a] + g_P[j1*P1C + a] + g_P[j2*P1C + a] + g_P[j3*P1C + a];
    }
    for (; p < e; p++) acc += g_P[g_csr[p]*P1C + a];
    g_B[row*P1C + a] = acc;
}

// ---------------- generic C += scale * A^T B, K-split via blockIdx.z -----------
__device__ __forceinline__ void gemm_AtB_dev(const float* __restrict__ A,
                                             const float* __restrict__ B,
                                             float* __restrict__ C,
                                             int K, int Mdim, int Ndim,
                                             int kPer, float scale) {
    __shared__ float As[16][65];
    __shared__ float Bs[16][65];
    int m0 = blockIdx.x * 64, n0 = blockIdx.y * 64;
    int k0 = blockIdx.z * kPer;
    int kEnd = min(K, k0 + kPer);
    int tid = threadIdx.x;
    int tx = tid & 15, ty = tid >> 4;
    float acc[4][4];
    #pragma unroll
    for (int i = 0; i < 4; i++)
        #pragma unroll
        for (int j = 0; j < 4; j++) acc[i][j] = 0.f;
    for (int kb = k0; kb < kEnd; kb += 16) {
        #pragma unroll
        for (int q = 0; q < 4; q++) {
            int idx = tid + q*256;
            int kk = idx >> 6, mm = idx & 63;
            int kg = kb + kk;
            As[kk][mm] = (kg < kEnd && (m0 + mm) < Mdim) ? A[kg*Mdim + m0 + mm] : 0.f;
            Bs[kk][mm] = (kg < kEnd && (n0 + mm) < Ndim) ? B[kg*Ndim + n0 + mm] : 0.f;
        }
        __syncthreads();
        #pragma unroll
        for (int kk = 0; kk < 16; kk++) {
            float av[4], bv[4];
            #pragma unroll
            for (int i = 0; i < 4; i++) av[i] = As[kk][ty*4 + i];
            #pragma unroll
            for (int j = 0; j < 4; j++) bv[j] = Bs[kk][tx*4 + j];
            #pragma unroll
            for (int i = 0; i < 4; i++)
                #pragma unroll
                for (int j = 0; j < 4; j++) acc[i][j] += av[i] * bv[j];
        }
        __syncthreads();
    }
    #pragma unroll
    for (int i = 0; i < 4; i++) {
        int m = m0 + ty*4 + i;
        if (m >= Mdim) continue;
        #pragma unroll
        for (int j = 0; j < 4; j++) {
            int n = n0 + tx*4 + j;
            if (n < Ndim) atomicAdd(&C[m*Ndim + n], acc[i][j] * scale);
        }
    }
}

__global__ void k_gemm_x1() { gemm_AtB_dev(g_P,  g_ze,  g_x1, NN,  P1C, DD,  125, (float)P1C/(float)NN); }
__global__ void k_gemm_A1() { gemm_AtB_dev(g_P,  g_B,   g_A1, NN,  P1C, P1C, 250, 1.f); }
__global__ void k_gemm_x2() { gemm_AtB_dev(g_P2, g_ze2, g_x2, P1C, P2C, DD,  64,  (float)P2C/(float)P1C); }

// ---------------- fused level-2: P2 = (x1@Wp2)*LOG_SCALE and T2 = x1@We2 -------
__global__ void k_PT2(const float* __restrict__ Wp2, const float* __restrict__ We2) {
    int idx = blockIdx.x * blockDim.x + threadIdx.x;
    if (idx < P1C*P2C) {
        int i = idx / P2C, a = idx % P2C;
        float acc = 0.f;
        for (int d = 0; d < DD; d++) acc += g_x1[i*DD + d] * Wp2[d*P2C + a];
        g_P2[idx] = acc * LOG_SCALE;
    } else {
        int r = idx - P1C*P2C;
        if (r >= P1C*DD) return;
        int i = r / DD, d = r % DD;
        float acc = 0.f;
        for (int k = 0; k < DD; k++) acc += g_x1[i*DD + k] * We2[k*DD + d];
        g_T2[r] = acc;
    }
}

__global__ void k_softmax2() {
    __shared__ float sm[256];
    int a = blockIdx.x, tid = threadIdx.x;
    float v = g_P2[tid*P2C + a];
    sm[tid] = v; __syncthreads();
    for (int s = 128; s; s >>= 1) { if (tid < s) sm[tid] = fmaxf(sm[tid], sm[tid+s]); __syncthreads(); }
    float mx = sm[0]; __syncthreads();
    float e = expf(v - mx);
    sm[tid] = e; __syncthreads();
    for (int s = 128; s; s >>= 1) { if (tid < s) sm[tid] += sm[tid+s]; __syncthreads(); }
    float Z = sm[0]; __syncthreads();
    float sv = e / Z;
    g_P2[tid*P2C + a] = sv;
    float ent = (sv > 0.f) ? -sv * logf(sv) : 0.f;
    sm[tid] = ent; __syncthreads();
    for (int s = 128; s; s >>= 1) { if (tid < s) sm[tid] += sm[tid+s]; __syncthreads(); }
    float E = sm[0]; __syncthreads();
    float ya = g_y1[tid] * sv;
    sm[tid] = ya; __syncthreads();
    for (int s = 128; s; s >>= 1) { if (tid < s) sm[tid] += sm[tid+s]; __syncthreads(); }
    if (tid == 0) {
        atomicAdd(&g_acc[3], E);
        g_y2[a] = sm[0] * ((float)P2C / (float)P1C);
    }
}

__global__ void k_ze2() {
    int i = blockIdx.x, d = threadIdx.x;
    float acc = 0.f;
    #pragma unroll 4
    for (int j = 0; j < P1C; j++) acc += g_A1[i*P1C + j] * g_T2[j*DD + d];
    g_ze2[i*DD + d] = tanhf(acc);
}

// ---------------- decoder: 8 rows/block, batched W1 loads ----------------------
__global__ void k_decoder(const float* __restrict__ y, const float* __restrict__ W1,
                          const float* __restrict__ W2, const float* __restrict__ b2) {
    __shared__ float zr[RPB][DD];
    __shared__ float yv[RPB];
    __shared__ float part[8][RPB][2];   // [warp][row][u|res]
    __shared__ float fin[RPB][2];
    int base = blockIdx.x * RPB;
    int tid = threadIdx.x;

    #pragma unroll
    for (int q = 0; q < 2; q++) {
        int idx = tid + q*256;
        int r = idx >> 6, d = idx & 63;
        int row = base + r;
        float v = 0.f;
        if (row < MMROWS) {
            const float* src = (row < NN) ? &g_z[row*DD]
                             : (row < NN+P1C ? &g_x1[(row-NN)*DD] : &g_x2[(row-NN-P1C)*DD]);
            v = src[d];
        }
        zr[r][d] = v;
    }
    if (tid < RPB) {
        int row = base + tid;
        float v = 0.f;
        if (row < MMROWS)
            v = (row < NN) ? y[row] : (row < NN+P1C ? g_y1[row-NN] : g_y2[row-NN-P1C]);
        yv[tid] = v;
    }
    __syncthreads();

    int h = tid;
    float bh  = g_b1p[h];
    float w2h = W2[h];
    float c1h = g_c1[h];
    float c2h = g_c2[h];

    float a[RPB];
    #pragma unroll
    for (int r = 0; r < RPB; r++) a[r] = bh;
    #pragma unroll
    for (int d0 = 0; d0 < DD; d0 += 8) {
        float w[8];
        #pragma unroll
        for (int k = 0; k < 8; k++) w[k] = W1[(9 + d0 + k)*HH + h];
        #pragma unroll
        for (int k = 0; k < 8; k++)
            #pragma unroll
            for (int r = 0; r < RPB; r++) a[r] += zr[r][d0+k] * w[k];
    }

    float uc[RPB], rc[RPB];
    #pragma unroll
    for (int r = 0; r < RPB; r++) {
        float th = tanhf(a[r]);
        float dh = 1.f - th*th;
        uc[r] = w2h * th;
        rc[r] = c1h * dh + 2.f * th * dh * c2h;
    }

    int lane = tid & 31, wrp = tid >> 5;
    #pragma unroll
    for (int r = 0; r < RPB; r++) {
        float u = uc[r], rr = rc[r];
        #pragma unroll
        for (int o = 16; o; o >>= 1) {
            u  += __shfl_xor_sync(0xffffffffu, u,  o);
            rr += __shfl_xor_sync(0xffffffffu, rr, o);
        }
        if (lane == 0) { part[wrp][r][0] = u; part[wrp][r][1] = rr; }
    }
    __syncthreads();

    if (tid < RPB) {
        int r = tid;
        float U = 0.f, R = 0.f;
        #pragma unroll
        for (int w = 0; w < 8; w++) { U += part[w][r][0]; R += part[w][r][1]; }
        int row = base + r;
        if (row < MMROWS) {
            float ed = U + b2[0] - yv[r];
            fin[r][0] = ed * ed;
            fin[r][1] = R * R;
        } else {
            fin[r][0] = 0.f; fin[r][1] = 0.f;
        }
    }
    __syncthreads();
    if (tid == 0) {
        float sd = 0.f, sp = 0.f;
        #pragma unroll
        for (int r = 0; r < RPB; r++) { sd += fin[r][0]; sp += fin[r][1]; }
        atomicAdd(&g_acc[0], sd);
        atomicAdd(&g_acc[1], sp);
    }
}

// ---------------- final scalar -------------------------------------------------
__global__ void k_final(float* __restrict__ out) {
    float loss = g_acc[0] / (float)MMROWS
               + g_acc[1] / (float)MMROWS
               + g_acc[2] / (float)(NN*P1C)
               + g_acc[3] / (float)(P1C*P2C);
    out[0] = loss;
}

// ---------------- launch --------------------------------------------------------
extern "C" void kernel_launch(void* const* d_in, const int* in_sizes, int n_in,
                              void* d_out, int out_size) {
    const float* x0   = (const float*)d_in[0];
    const int*   adj  = (const int*)  d_in[1];
    const float* t    = (const float*)d_in[2];
    const float* y    = (const float*)d_in[3];
    const float* Wenc = (const float*)d_in[4];
    const float* Wp1  = (const float*)d_in[5];
    const float* Wp2  = (const float*)d_in[6];
    const float* We1  = (const float*)d_in[7];
    const float* We2  = (const float*)d_in[8];
    const float* W1   = (const float*)d_in[9];
    const float* b1   = (const float*)d_in[10];
    const float* W2   = (const float*)d_in[11];
    const float* b2   = (const float*)d_in[12];
    float* out = (float*)d_out;

    k_zero_all<<<1024, 256>>>();
    k_prep<<<1, 256>>>(t, W1, b1, W2);
    k_encoder<<<NN/8, 256>>>(x0, Wenc);
    k_PT1<<<NN/8, 256>>>(Wp1, We1);
    k_dedup_count<<<(EE + 255)/256, 256>>>(adj);
    k_scan<<<1, 1024>>>();
    k_fill<<<(EE + 255)/256, 256>>>(adj);
    k_gather_ze<<<(NN + 3)/4, dim3(64, 4)>>>();
    k_soft1_partial<<<dim3(P1C/32, 20), dim3(32, 32)>>>();
    k_soft1_final<<<dim3(P1C/32, 20), dim3(32, 32)>>>(y);
    k_gather_B<<<NN, 256>>>();
    k_gemm_x1<<<dim3(4, 1, 40), 256>>>();
    k_gemm_A1<<<dim3(4, 4, 20), 256>>>();
    k_PT2<<<(P1C*P2C + P1C*DD + 255)/256, 256>>>(Wp2, We2);
    k_softmax2<<<P2C, 256>>>();
    k_ze2<<<P1C, DD>>>();
    k_gemm_x2<<<dim3(1, 1, 4), 256>>>();
    k_decoder<<<(MMROWS + RPB - 1)/RPB, 256>>>(y, W1, W2, b2);
    k_final<<<1, 1>>>(out);
}

// round 16
// speedup vs baseline: 1.6120x; 1.0712x over previous
#include <cuda_runtime.h>
#include <math.h>

#define NN 5000
#define EE 80000
#define FIN 32
#define DD 64
#define P1C 256
#define P2C 32
#define HH 256
#define MMROWS (NN + P1C + P2C)  /* 5288 */
#define LOG_SCALE 1.4763057f
#define BITWORDS ((NN*NN+31)/32)
#define RPB 8                     /* decoder rows per block */

// ---------------- scratch (__device__ globals; no allocation allowed) ----------
__device__ float g_z [NN*DD];
__device__ float g_P [NN*P1C];      // logits -> S (level 1), in place
__device__ float g_T1[NN*DD];
__device__ float g_ze[NN*DD];
__device__ float g_B [NN*P1C];      // A @ S
__device__ float g_x1[P1C*DD];
__device__ float g_A1[P1C*P1C];
__device__ float g_y1[P1C];
__device__ float g_colZ[P1C];
__device__ float g_P2[P1C*P2C];     // logits2 -> S2 in place
__device__ float g_T2[P1C*DD];
__device__ float g_ze2[P1C*DD];
__device__ float g_x2[P2C*DD];
__device__ float g_y2[P2C];
__device__ float g_b1p[HH], g_c1[HH], g_c2[HH];
__device__ float g_acc[8];          // 0:data 1:pde 2:ent1 3:ent2
__device__ unsigned g_bitmap[BITWORDS];
__device__ int g_deg[NN], g_cur[NN], g_offs[NN+1];
__device__ int g_csr[EE];
__device__ unsigned char g_keep[EE];

// ---------------- zero accumulators + (block 0) decoder constant prep ----------
__global__ void k_zero_all(const float* __restrict__ t, const float* __restrict__ W1,
                           const float* __restrict__ b1, const float* __restrict__ W2) {
    int i = blockIdx.x * blockDim.x + threadIdx.x;
    int st = gridDim.x * blockDim.x;
    for (int k = i; k < BITWORDS; k += st) g_bitmap[k] = 0u;
    for (int k = i; k < NN; k += st) { g_deg[k] = 0; g_cur[k] = 0; }
    for (int k = i; k < P1C*DD; k += st) g_x1[k] = 0.f;
    for (int k = i; k < P1C*P1C; k += st) g_A1[k] = 0.f;
    for (int k = i; k < P2C*DD; k += st) g_x2[k] = 0.f;
    for (int k = i; k < P1C; k += st) { g_y1[k] = 0.f; g_colZ[k] = 0.f; }
    if (i < 8) g_acc[i] = 0.f;

    if (blockIdx.x == 0) {        // fold t_enc into b1', c1, c2 (disjoint arrays)
        int h = threadIdx.x;
        float t0 = t[0];
        float te[6];
        te[0] = t0 / 1e2f;  te[1] = t0 / 1e3f;  te[2] = t0 / 1e4f;
        te[3] = logf(t0 / 1e-2f + 1.f);
        te[4] = logf(t0 / 1e-1f + 1.f);
        te[5] = logf(t0 / 1.0f  + 1.f);
        float b = b1[h];
        #pragma unroll
        for (int k = 0; k < 6; k++) b += te[k] * W1[k*HH + h];
        g_b1p[h] = b;
        float w2 = W2[h];
        g_c1[h] = w2 * W1[0*HH + h];
        float s = 0.f;
        #pragma unroll
        for (int k = 1; k < 9; k++) { float w = W1[k*HH + h]; s += w * w; }
        g_c2[h] = w2 * s;
    }
}

// ---------------- encoder: z = tanh(x0 @ W_enc[:, :64]) * LOG_SCALE ------------
__global__ void k_encoder(const float* __restrict__ x0, const float* __restrict__ Wenc) {
    __shared__ float xs[8][FIN];
    int i0 = blockIdx.x * 8;
    int tid = threadIdx.x;
    {
        int r = tid >> 5, c = tid & 31;
        xs[r][c] = x0[(i0 + r)*FIN + c];       // 625*8 = 5000 exact
    }
    __syncthreads();
    int a = tid & 63, rg = tid >> 6;
    float acc[2] = {0.f, 0.f};
    #pragma unroll
    for (int d0 = 0; d0 < FIN; d0 += 8) {
        float w[8];
        #pragma unroll
        for (int k = 0; k < 8; k++) w[k] = Wenc[(d0+k)*67 + a];
        #pragma unroll
        for (int k = 0; k < 8; k++) {
            acc[0] += xs[rg*2 + 0][d0+k] * w[k];
            acc[1] += xs[rg*2 + 1][d0+k] * w[k];
        }
    }
    #pragma unroll
    for (int r = 0; r < 2; r++)
        g_z[(i0 + rg*2 + r)*DD + a] = tanhf(acc[r]) * LOG_SCALE;
}

// ---------------- tiled GEMM for P = (z@Wp)*LOG_SCALE and T1 = z@We ------------
// grid (79, 5): by in [0,4) -> P tile cols by*64; by==4 -> T1.
// Full K=64 staged in shared; 4x4 register tile per thread.
__global__ void k_PT1(const float* __restrict__ Wp, const float* __restrict__ We) {
    __shared__ float As[64][68];   // z rows tile
    __shared__ float Bs[64][68];   // W tile (d-major)
    int m0 = blockIdx.x * 64;
    int by = blockIdx.y;
    const float* __restrict__ W = (by < 4) ? Wp : We;
    int ldW = (by < 4) ? P1C : DD;
    int n0  = (by < 4) ? by * 64 : 0;
    float scale = (by < 4) ? LOG_SCALE : 1.f;
    int tid = threadIdx.x;
    #pragma unroll
    for (int q = 0; q < 16; q++) {
        int idx = tid + q*256;
        int r = idx >> 6, c = idx & 63;
        int gr = m0 + r;
        As[r][c] = (gr < NN) ? g_z[gr*DD + c] : 0.f;
        Bs[r][c] = W[r*ldW + n0 + c];          // r = d index here
    }
    __syncthreads();
    int tx = tid & 15, ty = tid >> 4;
    float acc[4][4];
    #pragma unroll
    for (int i = 0; i < 4; i++)
        #pragma unroll
        for (int j = 0; j < 4; j++) acc[i][j] = 0.f;
    #pragma unroll 8
    for (int d = 0; d < DD; d++) {
        float av[4], bv[4];
        #pragma unroll
        for (int i = 0; i < 4; i++) av[i] = As[ty*4 + i][d];
        #pragma unroll
        for (int j = 0; j < 4; j++) bv[j] = Bs[d][tx*4 + j];
        #pragma unroll
        for (int i = 0; i < 4; i++)
            #pragma unroll
            for (int j = 0; j < 4; j++) acc[i][j] += av[i] * bv[j];
    }
    float* __restrict__ C = (by < 4) ? g_P : g_T1;
    int ldC = (by < 4) ? P1C : DD;
    #pragma unroll
    for (int i = 0; i < 4; i++) {
        int m = m0 + ty*4 + i;
        if (m < NN) {
            #pragma unroll
            for (int j = 0; j < 4; j++)
                C[m*ldC + n0 + tx*4 + j] = acc[i][j] * scale;
        }
    }
}

// ---------------- edge dedup (A = set(1.0) semantics) + degree count -----------
__global__ void k_dedup_count(const int* __restrict__ adj) {
    int e = blockIdx.x * blockDim.x + threadIdx.x;
    if (e >= EE) return;
    int i = adj[e], j = adj[EE + e];
    unsigned idx = (unsigned)i * NN + (unsigned)j;
    unsigned w = idx >> 5, b = 1u << (idx & 31);
    unsigned old = atomicOr(&g_bitmap[w], b);
    unsigned char kp = ((old & b) == 0u) ? 1 : 0;
    g_keep[e] = kp;
    if (kp) atomicAdd(&g_deg[i], 1);
}

// ---------------- exclusive scan of degrees (single block) ---------------------
__global__ void k_scan() {
    __shared__ int part[1024];
    int tid = threadIdx.x;
    int loc[5];
    int s = 0;
    #pragma unroll
    for (int k = 0; k < 5; k++) {
        int idx = tid*5 + k;
        int v = (idx < NN) ? g_deg[idx] : 0;
        loc[k] = s; s += v;
    }
    part[tid] = s;
    __syncthreads();
    for (int off = 1; off < 1024; off <<= 1) {
        int v = (tid >= off) ? part[tid - off] : 0;
        __syncthreads();
        part[tid] += v;
        __syncthreads();
    }
    int base = (tid > 0) ? part[tid - 1] : 0;
    #pragma unroll
    for (int k = 0; k < 5; k++) {
        int idx = tid*5 + k;
        if (idx < NN) g_offs[idx] = base + loc[k];
    }
    if (tid == 1023) g_offs[NN] = part[1023];
}

// ---------------- fill CSR column indices --------------------------------------
__global__ void k_fill(const int* __restrict__ adj) {
    int e = blockIdx.x * blockDim.x + threadIdx.x;
    if (e >= EE) return;
    if (!g_keep[e]) return;
    int i = adj[e], j = adj[EE + e];
    int p = atomicAdd(&g_cur[i], 1);
    g_csr[g_offs[i] + p] = j;
}

// ---------------- ze = tanh(A @ T1) via CSR gather (edge-unrolled x4) ----------
__global__ void k_gather_ze() {
    int row = blockIdx.x * 4 + threadIdx.y;
    if (row >= NN) return;
    int d = threadIdx.x;
    int s = g_offs[row], e = g_offs[row + 1];
    float acc = 0.f;
    int p = s;
    for (; p + 4 <= e; p += 4) {
        int j0 = g_csr[p], j1 = g_csr[p+1], j2 = g_csr[p+2], j3 = g_csr[p+3];
        acc += g_T1[j0*DD + d] + g_T1[j1*DD + d] + g_T1[j2*DD + d] + g_T1[j3*DD + d];
    }
    for (; p < e; p++) acc += g_T1[g_csr[p]*DD + d];
    g_ze[row*DD + d] = tanhf(acc);
}

// ---------------- softmax1 part 1: column sum of exp (no max; logits bounded) --
__global__ void k_soft1_partial() {
    __shared__ float sm[32][33];
    int txc = threadIdx.x, ty = threadIdx.y;
    int col = blockIdx.x * 32 + txc;
    int r0 = blockIdx.y * 250, r1 = r0 + 250;
    float z = 0.f;
    for (int i = r0 + ty; i < r1; i += 32) z += expf(g_P[i*P1C + col]);
    sm[ty][txc] = z; __syncthreads();
    for (int s = 16; s; s >>= 1) {
        if (ty < s) sm[ty][txc] += sm[ty+s][txc];
        __syncthreads();
    }
    if (ty == 0) atomicAdd(&g_colZ[col], sm[0][txc]);
}

// ---------------- softmax1 part 2: normalize + entropy + y-pool ----------------
__global__ void k_soft1_final(const float* __restrict__ y) {
    __shared__ float sm[32][33];
    int txc = threadIdx.x, ty = threadIdx.y;
    int col = blockIdx.x * 32 + txc;
    int r0 = blockIdx.y * 250, r1 = r0 + 250;
    float Z = g_colZ[col];
    float inv = 1.f / Z;
    float lZ  = logf(Z);
    float ent = 0.f, ya = 0.f;
    for (int i = r0 + ty; i < r1; i += 32) {
        float v  = g_P[i*P1C + col];
        float sv = expf(v) * inv;
        g_P[i*P1C + col] = sv;
        ent -= sv * (v - lZ);
        ya  += y[i] * sv;
    }
    sm[ty][txc] = ya; __syncthreads();
    for (int s = 16; s; s >>= 1) {
        if (ty < s) sm[ty][txc] += sm[ty+s][txc];
        __syncthreads();
    }
    if (ty == 0) atomicAdd(&g_y1[col], sm[0][txc] * ((float)P1C / (float)NN));
    __syncthreads();
    sm[ty][txc] = ent; __syncthreads();
    for (int s = 16; s; s >>= 1) {
        if (ty < s) sm[ty][txc] += sm[ty+s][txc];
        __syncthreads();
    }
    if (ty == 0) {
        float e = sm[0][txc];
        #pragma unroll
        for (int o = 16; o; o >>= 1) e += __shfl_xor_sync(0xffffffffu, e, o);
        if (txc == 0) atomicAdd(&g_acc[2], e);
    }
}

// ---------------- B = A @ S via CSR gather (edge-unrolled x4) ------------------
__global__ void k_gather_B() {
    int row = blockIdx.x, a = threadIdx.x;
    int s = g_offs[row], e = g_offs[row + 1];
    float acc = 0.f;
    int p = s;
    for (; p + 4 <= e; p += 4) {
        int j0 = g_csr[p], j1 = g_csr[p+1], j2 = g_csr[p+2], j3 = g_csr[p+3];
        acc += g_P[j0*P1C + a] + g_P[j1*P1C + a] + g_P[j2*P1C + a] + g_P[j3*P1C + a];
    }
    for (; p < e; p++) acc += g_P[g_csr[p]*P1C + a];
    g_B[row*P1C + a] = acc;
}

// ---------------- generic C += scale * A^T B, K-split via blockIdx.z -----------
__device__ __forceinline__ void gemm_AtB_dev(const float* __restrict__ A,
                                             const float* __restrict__ B,
                                             float* __restrict__ C,
                                             int K, int Mdim, int Ndim,
                                             int kPer, float scale) {
    __shared__ float As[16][65];
    __shared__ float Bs[16][65];
    int m0 = blockIdx.x * 64, n0 = blockIdx.y * 64;
    int k0 = blockIdx.z * kPer;
    int kEnd = min(K, k0 + kPer);
    int tid = threadIdx.x;
    int tx = tid & 15, ty = tid >> 4;
    float acc[4][4];
    #pragma unroll
    for (int i = 0; i < 4; i++)
        #pragma unroll
        for (int j = 0; j < 4; j++) acc[i][j] = 0.f;
    for (int kb = k0; kb < kEnd; kb += 16) {
        #pragma unroll
        for (int q = 0; q < 4; q++) {
            int idx = tid + q*256;
            int kk = idx >> 6, mm = idx & 63;
            int kg = kb + kk;
            As[kk][mm] = (kg < kEnd && (m0 + mm) < Mdim) ? A[kg*Mdim + m0 + mm] : 0.f;
            Bs[kk][mm] = (kg < kEnd && (n0 + mm) < Ndim) ? B[kg*Ndim + n0 + mm] : 0.f;
        }
        __syncthreads();
        #pragma unroll
        for (int kk = 0; kk < 16; kk++) {
            float av[4], bv[4];
            #pragma unroll
            for (int i = 0; i < 4; i++) av[i] = As[kk][ty*4 + i];
            #pragma unroll
            for (int j = 0; j < 4; j++) bv[j] = Bs[kk][tx*4 + j];
            #pragma unroll
            for (int i = 0; i < 4; i++)
                #pragma unroll
                for (int j = 0; j < 4; j++) acc[i][j] += av[i] * bv[j];
        }
        __syncthreads();
    }
    #pragma unroll
    for (int i = 0; i < 4; i++) {
        int m = m0 + ty*4 + i;
        if (m >= Mdim) continue;
        #pragma unroll
        for (int j = 0; j < 4; j++) {
            int n = n0 + tx*4 + j;
            if (n < Ndim) atomicAdd(&C[m*Ndim + n], acc[i][j] * scale);
        }
    }
}

__global__ void k_gemm_x1() { gemm_AtB_dev(g_P,  g_ze,  g_x1, NN,  P1C, DD,  125, (float)P1C/(float)NN); }
__global__ void k_gemm_A1() { gemm_AtB_dev(g_P,  g_B,   g_A1, NN,  P1C, P1C, 250, 1.f); }
__global__ void k_gemm_x2() { gemm_AtB_dev(g_P2, g_ze2, g_x2, P1C, P2C, DD,  64,  (float)P2C/(float)P1C); }

// ---------------- fused level-2: P2 = (x1@Wp2)*LOG_SCALE and T2 = x1@We2 -------
__global__ void k_PT2(const float* __restrict__ Wp2, const float* __restrict__ We2) {
    int idx = blockIdx.x * blockDim.x + threadIdx.x;
    if (idx < P1C*P2C) {
        int i = idx / P2C, a = idx % P2C;
        float acc = 0.f;
        for (int d = 0; d < DD; d++) acc += g_x1[i*DD + d] * Wp2[d*P2C + a];
        g_P2[idx] = acc * LOG_SCALE;
    } else {
        int r = idx - P1C*P2C;
        if (r >= P1C*DD) return;
        int i = r / DD, d = r % DD;
        float acc = 0.f;
        for (int k = 0; k < DD; k++) acc += g_x1[i*DD + k] * We2[k*DD + d];
        g_T2[r] = acc;
    }
}

__global__ void k_softmax2() {
    __shared__ float sm[256];
    int a = blockIdx.x, tid = threadIdx.x;
    float v = g_P2[tid*P2C + a];
    sm[tid] = v; __syncthreads();
    for (int s = 128; s; s >>= 1) { if (tid < s) sm[tid] = fmaxf(sm[tid], sm[tid+s]); __syncthreads(); }
    float mx = sm[0]; __syncthreads();
    float e = expf(v - mx);
    sm[tid] = e; __syncthreads();
    for (int s = 128; s; s >>= 1) { if (tid < s) sm[tid] += sm[tid+s]; __syncthreads(); }
    float Z = sm[0]; __syncthreads();
    float sv = e / Z;
    g_P2[tid*P2C + a] = sv;
    float ent = (sv > 0.f) ? -sv * logf(sv) : 0.f;
    sm[tid] = ent; __syncthreads();
    for (int s = 128; s; s >>= 1) { if (tid < s) sm[tid] += sm[tid+s]; __syncthreads(); }
    float E = sm[0]; __syncthreads();
    float ya = g_y1[tid] * sv;
    sm[tid] = ya; __syncthreads();
    for (int s = 128; s; s >>= 1) { if (tid < s) sm[tid] += sm[tid+s]; __syncthreads(); }
    if (tid == 0) {
        atomicAdd(&g_acc[3], E);
        g_y2[a] = sm[0] * ((float)P2C / (float)P1C);
    }
}

__global__ void k_ze2() {
    int i = blockIdx.x, d = threadIdx.x;
    float acc = 0.f;
    #pragma unroll 4
    for (int j = 0; j < P1C; j++) acc += g_A1[i*P1C + j] * g_T2[j*DD + d];
    g_ze2[i*DD + d] = tanhf(acc);
}

// ---------------- decoder: 8 rows/block, batched W1 loads ----------------------
__global__ void k_decoder(const float* __restrict__ y, const float* __restrict__ W1,
                          const float* __restrict__ W2, const float* __restrict__ b2) {
    __shared__ float zr[RPB][DD];
    __shared__ float yv[RPB];
    __shared__ float part[8][RPB][2];
    __shared__ float fin[RPB][2];
    int base = blockIdx.x * RPB;
    int tid = threadIdx.x;

    #pragma unroll
    for (int q = 0; q < 2; q++) {
        int idx = tid + q*256;
        int r = idx >> 6, d = idx & 63;
        int row = base + r;
        float v = 0.f;
        if (row < MMROWS) {
            const float* src = (row < NN) ? &g_z[row*DD]
                             : (row < NN+P1C ? &g_x1[(row-NN)*DD] : &g_x2[(row-NN-P1C)*DD]);
            v = src[d];
        }
        zr[r][d] = v;
    }
    if (tid < RPB) {
        int row = base + tid;
        float v = 0.f;
        if (row < MMROWS)
            v = (row < NN) ? y[row] : (row < NN+P1C ? g_y1[row-NN] : g_y2[row-NN-P1C]);
        yv[tid] = v;
    }
    __syncthreads();

    int h = tid;
    float bh  = g_b1p[h];
    float w2h = W2[h];
    float c1h = g_c1[h];
    float c2h = g_c2[h];

    float a[RPB];
    #pragma unroll
    for (int r = 0; r < RPB; r++) a[r] = bh;
    #pragma unroll
    for (int d0 = 0; d0 < DD; d0 += 8) {
        float w[8];
        #pragma unroll
        for (int k = 0; k < 8; k++) w[k] = W1[(9 + d0 + k)*HH + h];
        #pragma unroll
        for (int k = 0; k < 8; k++)
            #pragma unroll
            for (int r = 0; r < RPB; r++) a[r] += zr[r][d0+k] * w[k];
    }

    float uc[RPB], rc[RPB];
    #pragma unroll
    for (int r = 0; r < RPB; r++) {
        float th = tanhf(a[r]);
        float dh = 1.f - th*th;
        uc[r] = w2h * th;
        rc[r] = c1h * dh + 2.f * th * dh * c2h;
    }

    int lane = tid & 31, wrp = tid >> 5;
    #pragma unroll
    for (int r = 0; r < RPB; r++) {
        float u = uc[r], rr = rc[r];
        #pragma unroll
        for (int o = 16; o; o >>= 1) {
            u  += __shfl_xor_sync(0xffffffffu, u,  o);
            rr += __shfl_xor_sync(0xffffffffu, rr, o);
        }
        if (lane == 0) { part[wrp][r][0] = u; part[wrp][r][1] = rr; }
    }
    __syncthreads();

    if (tid < RPB) {
        int r = tid;
        float U = 0.f, R = 0.f;
        #pragma unroll
        for (int w = 0; w < 8; w++) { U += part[w][r][0]; R += part[w][r][1]; }
        int row = base + r;
        if (row < MMROWS) {
            float ed = U + b2[0] - yv[r];
            fin[r][0] = ed * ed;
            fin[r][1] = R * R;
        } else {
            fin[r][0] = 0.f; fin[r][1] = 0.f;
        }
    }
    __syncthreads();
    if (tid == 0) {
        float sd = 0.f, sp = 0.f;
        #pragma unroll
        for (int r = 0; r < RPB; r++) { sd += fin[r][0]; sp += fin[r][1]; }
        atomicAdd(&g_acc[0], sd);
        atomicAdd(&g_acc[1], sp);
    }
}

// ---------------- final scalar -------------------------------------------------
__global__ void k_final(float* __restrict__ out) {
    float loss = g_acc[0] / (float)MMROWS
               + g_acc[1] / (float)MMROWS
               + g_acc[2] / (float)(NN*P1C)
               + g_acc[3] / (float)(P1C*P2C);
    out[0] = loss;
}

// ---------------- launch --------------------------------------------------------
extern "C" void kernel_launch(void* const* d_in, const int* in_sizes, int n_in,
                              void* d_out, int out_size) {
    const float* x0   = (const float*)d_in[0];
    const int*   adj  = (const int*)  d_in[1];
    const float* t    = (const float*)d_in[2];
    const float* y    = (const float*)d_in[3];
    const float* Wenc = (const float*)d_in[4];
    const float* Wp1  = (const float*)d_in[5];
    const float* Wp2  = (const float*)d_in[6];
    const float* We1  = (const float*)d_in[7];
    const float* We2  = (const float*)d_in[8];
    const float* W1   = (const float*)d_in[9];
    const float* b1   = (const float*)d_in[10];
    const float* W2   = (const float*)d_in[11];
    const float* b2   = (const float*)d_in[12];
    float* out = (float*)d_out;

    k_zero_all<<<1024, 256>>>(t, W1, b1, W2);
    k_encoder<<<NN/8, 256>>>(x0, Wenc);
    k_PT1<<<dim3((NN + 63)/64, 5), 256>>>(Wp1, We1);
    k_dedup_count<<<(EE + 255)/256, 256>>>(adj);
    k_scan<<<1, 1024>>>();
    k_fill<<<(EE + 255)/256, 256>>>(adj);
    k_gather_ze<<<(NN + 3)/4, dim3(64, 4)>>>();
    k_soft1_partial<<<dim3(P1C/32, 20), dim3(32, 32)>>>();
    k_soft1_final<<<dim3(P1C/32, 20), dim3(32, 32)>>>(y);
    k_gather_B<<<NN, 256>>>();
    k_gemm_x1<<<dim3(4, 1, 40), 256>>>();
    k_gemm_A1<<<dim3(4, 4, 20), 256>>>();
    k_PT2<<<(P1C*P2C + P1C*DD + 255)/256, 256>>>(Wp2, We2);
    k_softmax2<<<P2C, 256>>>();
    k_ze2<<<P1C, DD>>>();
    k_gemm_x2<<<dim3(1, 1, 4), 256>>>();
    k_decoder<<<(MMROWS + RPB - 1)/RPB, 256>>>(y, W1, W2, b2);
    k_final<<<1, 1>>>(out);
}